// round 13
// baseline (speedup 1.0000x reference)
#include <cuda_runtime.h>

// Problem constants (fixed by the reference).
#define B_ROWS 16
#define D_LEN  2097152            // floats per row
#define D4_LEN (D_LEN / 4)        // float4 per row = 524288
#define BLOCKS_PER_ROW 148        // 148 SMs * 8 CTA/SM = 1184; 2368 = exactly 2 waves
#define THREADS 256
#define ROW_STRIDE (BLOCKS_PER_ROW * THREADS)        // 37888
#define FULL_ITERS (D4_LEN / ROW_STRIDE)             // 13
#define TAIL_LIMIT (D4_LEN - FULL_ITERS * ROW_STRIDE) // 31744: bases below this do a 14th elem
#define TOTAL_BLOCKS (B_ROWS * BLOCKS_PER_ROW)       // 2368

// Deterministic scratch: per-(row, block) partial sum of squared diffs.
__device__ float g_partial[TOTAL_BLOCKS];
// Completion counter for the fused last-block finalize. Reset to 0 by the
// finalizing block each run so every graph replay sees identical state.
__device__ unsigned int g_count = 0;

__global__ __launch_bounds__(THREADS)
void euclid_loss_kernel(const float4* __restrict__ out,
                        const float4* __restrict__ lab,
                        float* __restrict__ result) {
    const int row = blockIdx.y;
    const int blk = blockIdx.x;
    const int tbase = blk * THREADS + threadIdx.x;        // 0 .. ROW_STRIDE-1
    const size_t base = (size_t)row * D4_LEN + tbase;

    float acc = 0.0f;
    // 13 unconditional full-unroll float4-pair iterations (proven best load
    // shape), plus one predicated tail iteration covering the ragged 31744.
    #pragma unroll
    for (int i = 0; i < FULL_ITERS; i++) {
        float4 a = __ldg(&out[base + (size_t)i * ROW_STRIDE]);
        float4 b = __ldg(&lab[base + (size_t)i * ROW_STRIDE]);
        float dx = a.x - b.x;
        float dy = a.y - b.y;
        float dz = a.z - b.z;
        float dw = a.w - b.w;
        acc = fmaf(dx, dx, acc);
        acc = fmaf(dy, dy, acc);
        acc = fmaf(dz, dz, acc);
        acc = fmaf(dw, dw, acc);
    }
    if (tbase < TAIL_LIMIT) {
        float4 a = __ldg(&out[base + (size_t)FULL_ITERS * ROW_STRIDE]);
        float4 b = __ldg(&lab[base + (size_t)FULL_ITERS * ROW_STRIDE]);
        float dx = a.x - b.x;
        float dy = a.y - b.y;
        float dz = a.z - b.z;
        float dw = a.w - b.w;
        acc = fmaf(dx, dx, acc);
        acc = fmaf(dy, dy, acc);
        acc = fmaf(dz, dz, acc);
        acc = fmaf(dw, dw, acc);
    }

    // Block reduction: warp shuffle, then shared across 8 warps.
    __shared__ float s_warp[THREADS / 32];
    #pragma unroll
    for (int off = 16; off > 0; off >>= 1)
        acc += __shfl_xor_sync(0xFFFFFFFFu, acc, off);
    const int lane = threadIdx.x & 31;
    const int wid  = threadIdx.x >> 5;
    if (lane == 0) s_warp[wid] = acc;
    __syncthreads();

    __shared__ bool s_last;
    if (threadIdx.x == 0) {
        float v = 0.0f;
        #pragma unroll
        for (int w = 0; w < THREADS / 32; w++) v += s_warp[w];
        g_partial[row * BLOCKS_PER_ROW + blk] = v;
        // Release our partial, then announce completion.
        __threadfence();
        unsigned int prev = atomicAdd(&g_count, 1u);
        s_last = (prev == TOTAL_BLOCKS - 1);
    }
    __syncthreads();

    if (!s_last) return;

    // ---- Last block: deterministic finalize over all 2368 partials ----
    // 8 warps; warp w reduces rows 2w and 2w+1 (148 partials each).
    __shared__ float s_dist[B_ROWS];
    #pragma unroll
    for (int rr = 0; rr < 2; rr++) {
        const int r = wid * 2 + rr;
        const float* p = &g_partial[r * BLOCKS_PER_ROW];
        float v = __ldcg(&p[lane]) + __ldcg(&p[lane + 32])
                + __ldcg(&p[lane + 64]) + __ldcg(&p[lane + 96]);
        if (lane < BLOCKS_PER_ROW - 128)               // 148 - 128 = 20 extras
            v += __ldcg(&p[lane + 128]);
        #pragma unroll
        for (int off = 16; off > 0; off >>= 1)
            v += __shfl_xor_sync(0xFFFFFFFFu, v, off);
        if (lane == 0) s_dist[r] = sqrtf(v);
    }
    __syncthreads();

    if (threadIdx.x == 0) {
        float sum = 0.0f;
        #pragma unroll
        for (int r = 0; r < B_ROWS; r++) sum += s_dist[r];
        result[0] = sum / (float)B_ROWS;
        // Reset counter for the next (graph-replayed) invocation.
        g_count = 0;
    }
}

extern "C" void kernel_launch(void* const* d_in, const int* in_sizes, int n_in,
                              void* d_out, int out_size) {
    const float4* out = (const float4*)d_in[0];
    const float4* lab = (const float4*)d_in[1];
    float* res = (float*)d_out;

    dim3 grid(BLOCKS_PER_ROW, B_ROWS);
    euclid_loss_kernel<<<grid, THREADS>>>(out, lab, res);
}